// round 12
// baseline (speedup 1.0000x reference)
#include <cuda_runtime.h>

// Demolition_Conv2d: grouped conv (16 groups of 1->32, 3x3, pad 1) + bias,
// per-(cin,cout) 5-bit quant-dequant (scale=15/9), sum over cin.
//
// R12: R10 (cin-pair planes, vertical 4-px slots, NC=4) + occupancy 5
// blocks/SM (launch_bounds(128,5)). NO prefetch (R11 showed it pollutes
// L1/L2 for negative gain).

#define CIN   16
#define COUT  32
#define HH    112
#define WW    112
#define NB    8
#define NCP   8      // cin pairs
#define HP    114    // padded height
#define WP    114    // padded width
#define NC    4      // couts per thread
#define NS    4      // vertical pixel slots per thread

typedef unsigned long long f2;

__device__ __align__(16) f2 g_X[NB * NCP * HP * WP];   // ~6.65 MB packed planes

__device__ __forceinline__ f2 pk2(float lo, float hi) {
    f2 r; asm("mov.b64 %0, {%1, %2};" : "=l"(r) : "f"(lo), "f"(hi)); return r;
}
__device__ __forceinline__ void fma2i(f2& acc, f2 a, f2 b) {
    asm("fma.rn.f32x2 %0, %1, %2, %0;" : "+l"(acc) : "l"(a), "l"(b));
}
__device__ __forceinline__ void add2i(f2& acc, f2 b) {
    asm("add.rn.f32x2 %0, %0, %1;" : "+l"(acc) : "l"(b));
}
__device__ __forceinline__ float lanesum(f2 a) {
    float lo, hi;
    asm("mov.b64 {%0, %1}, %2;" : "=f"(lo), "=f"(hi) : "l"(a));
    return lo + hi;
}

// ---------------- prepass: padded cin-pair planes (2 pairs/thread) --------
#define PPW 57   // wp pairs per row
__global__ __launch_bounds__(256)
void prepass_kernel(const float* __restrict__ x)
{
    int gid = blockIdx.x * 256 + threadIdx.x;    // [0, NB*NCP*HP*PPW)
    if (gid >= NB * NCP * HP * PPW) return;
    int pp = gid % PPW;
    int t  = gid / PPW;
    int hp = t % HP;
    int t2 = t / HP;
    int cp = t2 % NCP;
    int b  = t2 / NCP;

    int h = hp - 1;
    bool rv = (h >= 0) && (h < HH);
    const float* p0 = x + (((b * CIN + 2 * cp)     * HH + h) * WW);
    const float* p1 = x + (((b * CIN + 2 * cp + 1) * HH + h) * WW);

    ulonglong2 outv;
    int w0 = 2 * pp - 1;
    int w1 = 2 * pp;
    bool v0 = rv && (w0 >= 0) && (w0 < WW);
    bool v1 = rv && (w1 >= 0) && (w1 < WW);
    outv.x = v0 ? pk2(p0[w0], p1[w0]) : 0ULL;
    outv.y = v1 ? pk2(p0[w1], p1[w1]) : 0ULL;

    ulonglong2* dst = reinterpret_cast<ulonglong2*>(
        g_X + ((long)((b * NCP + cp) * HP + hp)) * WP) + pp;
    *dst = outv;
}

// ---------------- main kernel ----------------
// 200704 threads = 1568 blocks x 128. grp = g/25088 uniform per block
// (25088 = 196*128). q = g%25088 -> (b, band, w): w = q%112,
// band = (q/112)%28, b = q/3136, h0 = band*4.
__global__ __launch_bounds__(128, 5)
void demolition_conv2d_kernel(const float* __restrict__ Wt,
                              const float* __restrict__ bias,
                              float* __restrict__ out)
{
    __shared__ __align__(16) f2 sW[NCP * NC * 10];   // 2560 B

    const float SCALEf = 15.0f / 9.0f;
    const float INVf   = 9.0f / 15.0f;
    const float MAGICf = 12582912.0f;   // 1.5 * 2^23

    int g = blockIdx.x * 128 + threadIdx.x;
    int grp = g / 25088;                 // 0..7, uniform per block
    int q   = g % 25088;
    int w    = q % WW;
    int band = (q / WW) % 28;
    int b    = q / (WW * 28);
    int h0   = band * NS;
    int co_base = grp * NC;

    for (int i = threadIdx.x; i < NCP * NC * 10; i += 128) {
        int e  = i / 10;
        int k  = i % 10;
        int cp = e / NC;
        int lc = e % NC;
        int co = co_base + lc;
        float v0, v1;
        if (k < 9) {
            v0 = Wt[((2 * cp)     * COUT + co) * 9 + k];
            v1 = Wt[((2 * cp + 1) * COUT + co) * 9 + k];
        } else {
            v0 = bias[(2 * cp)     * COUT + co];
            v1 = bias[(2 * cp + 1) * COUT + co];
        }
        sW[i] = pk2(v0 * SCALEf, v1 * SCALEf);
    }
    __syncthreads();

    const f2 MAG2  = pk2(MAGICf,  MAGICf);
    const f2 NMAG2 = pk2(-MAGICf, -MAGICf);

    f2 acc[NC][NS];
#pragma unroll
    for (int c = 0; c < NC; ++c)
#pragma unroll
        for (int s = 0; s < NS; ++s) acc[c][s] = 0ULL;

    // Padded plane pointer for cp=0: rows h0..h0+5 cover outputs h0..h0+3.
    const f2* A = g_X + ((long)b * NCP * HP + h0) * WP + w;
    const long PSTRIDE = (long)HP * WP;

#pragma unroll 1
    for (int cp = 0; cp < NCP; ++cp) {
        // 6 rows x 3 cols of taps (coalesced LDG.64 in w).
        f2 tp[6][3];
#pragma unroll
        for (int r = 0; r < 6; ++r) {
#pragma unroll
            for (int k = 0; k < 3; ++k)
                tp[r][k] = A[r * WP + k];
        }
        A += PSTRIDE;

        const ulonglong2* wb =
            reinterpret_cast<const ulonglong2*>(&sW[cp * NC * 10]);

#pragma unroll
        for (int c = 0; c < NC; ++c) {
            ulonglong2 w01 = wb[c * 5 + 0];   // w0, w1
            ulonglong2 w23 = wb[c * 5 + 1];   // w2, w3
            ulonglong2 w45 = wb[c * 5 + 2];   // w4, w5
            ulonglong2 w67 = wb[c * 5 + 3];   // w6, w7
            ulonglong2 w8b = wb[c * 5 + 4];   // w8, bias

#pragma unroll
            for (int s = 0; s < NS; ++s) {
                f2 y = w8b.y;
                fma2i(y, tp[s][0],     w01.x);
                fma2i(y, tp[s][1],     w01.y);
                fma2i(y, tp[s][2],     w23.x);
                fma2i(y, tp[s + 1][0], w23.y);
                fma2i(y, tp[s + 1][1], w45.x);
                fma2i(y, tp[s + 1][2], w45.y);
                fma2i(y, tp[s + 2][0], w67.x);
                fma2i(y, tp[s + 2][1], w67.y);
                fma2i(y, tp[s + 2][2], w8b.x);

                add2i(y, MAG2);           // per-lane RNE -> integer
                add2i(y, NMAG2);
                add2i(acc[c][s], y);      // exact integer-valued sums
            }
        }
    }

    // Stores: scalar, coalesced in w. 16 stores (4 couts x 4 rows).
#pragma unroll
    for (int c = 0; c < NC; ++c) {
        int co = co_base + c;
        float* ob = out + ((long)(b * COUT + co) * HH + h0) * WW + w;
#pragma unroll
        for (int s = 0; s < NS; ++s)
            ob[s * WW] = lanesum(acc[c][s]) * INVf;
    }
}

extern "C" void kernel_launch(void* const* d_in, const int* in_sizes, int n_in,
                              void* d_out, int out_size)
{
    const float* x    = (const float*)d_in[0];   // [8,16,112,112]
    const float* Wt   = (const float*)d_in[1];   // [16,32,1,3,3]
    const float* bias = (const float*)d_in[2];   // [16,32]
    float* out        = (float*)d_out;           // [8,32,112,112]

    // NB*NCP*HP*PPW = 415872 -> 1625 blocks of 256 (guarded).
    prepass_kernel<<<1625, 256>>>(x);
    // 200704 threads = 1568 blocks * 128.
    demolition_conv2d_kernel<<<1568, 128>>>(Wt, bias, out);
}

// round 13
// speedup vs baseline: 1.0589x; 1.0589x over previous
#include <cuda_runtime.h>

// Demolition_Conv2d: grouped conv (16 groups of 1->32, 3x3, pad 1) + bias,
// per-(cin,cout) 5-bit quant-dequant (scale=15/9), sum over cin.
//
// R13: R10 base (cin-pair planes, vertical 4-px slots, NC=4, occ 4) plus:
//  - warp-staggered cp start (de-phase L1tex LDG bursts across warps)
//  - paired +MAG/-MAG rounding (2 adds/partial instead of 3; exact RNE)
//  - cout-group fastest in blockIdx (wave-local L2 reuse of taps)

#define CIN   16
#define COUT  32
#define HH    112
#define WW    112
#define NB    8
#define NCP   8      // cin pairs
#define HP    114    // padded height
#define WP    114    // padded width
#define NC    4      // couts per thread
#define NS    4      // vertical pixel slots per thread

typedef unsigned long long f2;

__device__ __align__(16) f2 g_X[NB * NCP * HP * WP];   // ~6.65 MB packed planes

__device__ __forceinline__ f2 pk2(float lo, float hi) {
    f2 r; asm("mov.b64 %0, {%1, %2};" : "=l"(r) : "f"(lo), "f"(hi)); return r;
}
__device__ __forceinline__ void fma2i(f2& acc, f2 a, f2 b) {
    asm("fma.rn.f32x2 %0, %1, %2, %0;" : "+l"(acc) : "l"(a), "l"(b));
}
__device__ __forceinline__ void add2i(f2& acc, f2 b) {
    asm("add.rn.f32x2 %0, %0, %1;" : "+l"(acc) : "l"(b));
}
__device__ __forceinline__ float lanesum(f2 a) {
    float lo, hi;
    asm("mov.b64 {%0, %1}, %2;" : "=f"(lo), "=f"(hi) : "l"(a));
    return lo + hi;
}

// ---------------- prepass: padded cin-pair planes (2 pairs/thread) --------
#define PPW 57   // wp pairs per row
__global__ __launch_bounds__(256)
void prepass_kernel(const float* __restrict__ x)
{
    int gid = blockIdx.x * 256 + threadIdx.x;    // [0, NB*NCP*HP*PPW)
    if (gid >= NB * NCP * HP * PPW) return;
    int pp = gid % PPW;
    int t  = gid / PPW;
    int hp = t % HP;
    int t2 = t / HP;
    int cp = t2 % NCP;
    int b  = t2 / NCP;

    int h = hp - 1;
    bool rv = (h >= 0) && (h < HH);
    const float* p0 = x + (((b * CIN + 2 * cp)     * HH + h) * WW);
    const float* p1 = x + (((b * CIN + 2 * cp + 1) * HH + h) * WW);

    ulonglong2 outv;
    int w0 = 2 * pp - 1;
    int w1 = 2 * pp;
    bool v0 = rv && (w0 >= 0) && (w0 < WW);
    bool v1 = rv && (w1 >= 0) && (w1 < WW);
    outv.x = v0 ? pk2(p0[w0], p1[w0]) : 0ULL;
    outv.y = v1 ? pk2(p0[w1], p1[w1]) : 0ULL;

    ulonglong2* dst = reinterpret_cast<ulonglong2*>(
        g_X + ((long)((b * NCP + cp) * HP + hp)) * WP) + pp;
    *dst = outv;
}

// ---------------- main kernel ----------------
// 1568 blocks = 196 pixel-blocks x 8 cout groups (group fastest).
__global__ __launch_bounds__(128, 4)
void demolition_conv2d_kernel(const float* __restrict__ Wt,
                              const float* __restrict__ bias,
                              float* __restrict__ out)
{
    __shared__ __align__(16) f2 sW[NCP * NC * 10];   // 2560 B

    const float SCALEf = 15.0f / 9.0f;
    const float INVf   = 9.0f / 15.0f;
    const float MAGICf = 12582912.0f;   // 1.5 * 2^23

    int grp = blockIdx.x & 7;            // cout group, fastest
    int pb  = blockIdx.x >> 3;           // pixel block 0..195
    int q   = pb * 128 + threadIdx.x;    // [0, 25088)
    int w    = q % WW;
    int band = (q / WW) % 28;
    int b    = q / (WW * 28);
    int h0   = band * NS;
    int co_base = grp * NC;

    for (int i = threadIdx.x; i < NCP * NC * 10; i += 128) {
        int e  = i / 10;
        int k  = i % 10;
        int cp = e / NC;
        int lc = e % NC;
        int co = co_base + lc;
        float v0, v1;
        if (k < 9) {
            v0 = Wt[((2 * cp)     * COUT + co) * 9 + k];
            v1 = Wt[((2 * cp + 1) * COUT + co) * 9 + k];
        } else {
            v0 = bias[(2 * cp)     * COUT + co];
            v1 = bias[(2 * cp + 1) * COUT + co];
        }
        sW[i] = pk2(v0 * SCALEf, v1 * SCALEf);
    }
    __syncthreads();

    const f2 MAG2  = pk2(MAGICf,  MAGICf);
    const f2 NMAG2 = pk2(-MAGICf, -MAGICf);

    f2 acc[NC][NS];
#pragma unroll
    for (int c = 0; c < NC; ++c)
#pragma unroll
        for (int s = 0; s < NS; ++s) acc[c][s] = 0ULL;

    const long PSTRIDE = (long)HP * WP;
    const f2* plane0 = g_X + (long)b * NCP * PSTRIDE + (long)h0 * WP + w;

    // Warp-staggered cp start (even offset keeps +/-MAG parity = k parity).
    int cp0 = ((threadIdx.x >> 5) & 3) * 2;

#pragma unroll 2
    for (int k = 0; k < NCP; ++k) {
        int cp = (cp0 + k) & 7;
        const f2* A = plane0 + cp * PSTRIDE;
        // Alternating magic constant: exact RNE round + telescoping bias.
        const f2 MK = (k & 1) ? NMAG2 : MAG2;

        // 6 rows x 3 cols of taps (coalesced LDG.64 in w).
        f2 tp[6][3];
#pragma unroll
        for (int r = 0; r < 6; ++r) {
#pragma unroll
            for (int kk = 0; kk < 3; ++kk)
                tp[r][kk] = A[r * WP + kk];
        }

        const ulonglong2* wb =
            reinterpret_cast<const ulonglong2*>(&sW[cp * NC * 10]);

#pragma unroll
        for (int c = 0; c < NC; ++c) {
            ulonglong2 w01 = wb[c * 5 + 0];   // w0, w1
            ulonglong2 w23 = wb[c * 5 + 1];   // w2, w3
            ulonglong2 w45 = wb[c * 5 + 2];   // w4, w5
            ulonglong2 w67 = wb[c * 5 + 3];   // w6, w7
            ulonglong2 w8b = wb[c * 5 + 4];   // w8, bias

#pragma unroll
            for (int s = 0; s < NS; ++s) {
                f2 y = w8b.y;
                fma2i(y, tp[s][0],     w01.x);
                fma2i(y, tp[s][1],     w01.y);
                fma2i(y, tp[s][2],     w23.x);
                fma2i(y, tp[s + 1][0], w23.y);
                fma2i(y, tp[s + 1][1], w45.x);
                fma2i(y, tp[s + 1][2], w45.y);
                fma2i(y, tp[s + 2][0], w67.x);
                fma2i(y, tp[s + 2][1], w67.y);
                fma2i(y, tp[s + 2][2], w8b.x);

                // k even: y+MAG = MAG + q (exact); k odd: y-MAG = q - MAG.
                // Partial sums telescope exactly; after 8 cps acc = sum(q).
                add2i(y, MK);
                add2i(acc[c][s], y);
            }
        }
    }

    // Stores: scalar, coalesced in w. 16 stores (4 couts x 4 rows).
#pragma unroll
    for (int c = 0; c < NC; ++c) {
        int co = co_base + c;
        float* ob = out + ((long)(b * COUT + co) * HH + h0) * WW + w;
#pragma unroll
        for (int s = 0; s < NS; ++s)
            ob[s * WW] = lanesum(acc[c][s]) * INVf;
    }
}

extern "C" void kernel_launch(void* const* d_in, const int* in_sizes, int n_in,
                              void* d_out, int out_size)
{
    const float* x    = (const float*)d_in[0];   // [8,16,112,112]
    const float* Wt   = (const float*)d_in[1];   // [16,32,1,3,3]
    const float* bias = (const float*)d_in[2];   // [16,32]
    float* out        = (float*)d_out;           // [8,32,112,112]

    // NB*NCP*HP*PPW = 415872 -> 1625 blocks of 256 (guarded).
    prepass_kernel<<<1625, 256>>>(x);
    // 200704 threads = 1568 blocks * 128.
    demolition_conv2d_kernel<<<1568, 128>>>(Wt, bias, out);
}

// round 14
// speedup vs baseline: 1.1242x; 1.0616x over previous
#include <cuda_runtime.h>

// Demolition_Conv2d: grouped conv (16 groups of 1->32, 3x3, pad 1) + bias,
// per-(cin,cout) 5-bit quant-dequant (scale=15/9), sum over cin.
//
// R14: R10 base (cin-pair planes, vertical 4-px slots, NC=4, occ 4) with the
// quant-accumulate moved to the ALU pipe: t = y + MAGIC makes each lane's
// bits equal 0x4B400000 + q (q = RNE integer); accumulate RAW BITS with
// integer adds (alu pipe), strip 16*0x4B400000 once at the end (mod-2^32
// wraps cancel). fma-pipe ops per partial: 12 -> 10.

#define CIN   16
#define COUT  32
#define HH    112
#define WW    112
#define NB    8
#define NCP   8      // cin pairs
#define HP    114    // padded height
#define WP    114    // padded width
#define NC    4      // couts per thread
#define NS    4      // vertical pixel slots per thread

typedef unsigned long long f2;

__device__ __align__(16) f2 g_X[NB * NCP * HP * WP];   // ~6.65 MB packed planes

__device__ __forceinline__ f2 pk2(float lo, float hi) {
    f2 r; asm("mov.b64 %0, {%1, %2};" : "=l"(r) : "f"(lo), "f"(hi)); return r;
}
__device__ __forceinline__ void fma2i(f2& acc, f2 a, f2 b) {
    asm("fma.rn.f32x2 %0, %1, %2, %0;" : "+l"(acc) : "l"(a), "l"(b));
}
__device__ __forceinline__ void add2i(f2& acc, f2 b) {
    asm("add.rn.f32x2 %0, %0, %1;" : "+l"(acc) : "l"(b));
}
// accumulate the two 32-bit lane bit-patterns of t into integer accumulators
__device__ __forceinline__ void addbits(unsigned& aLo, unsigned& aHi, f2 t) {
    unsigned lo, hi;
    asm("mov.b64 {%0, %1}, %2;" : "=r"(lo), "=r"(hi) : "l"(t));
    aLo += lo;           // IADD3 on alu pipe
    aHi += hi;
}

// ---------------- prepass: padded cin-pair planes (2 pairs/thread) --------
#define PPW 57   // wp pairs per row
__global__ __launch_bounds__(256)
void prepass_kernel(const float* __restrict__ x)
{
    int gid = blockIdx.x * 256 + threadIdx.x;    // [0, NB*NCP*HP*PPW)
    if (gid >= NB * NCP * HP * PPW) return;
    int pp = gid % PPW;
    int t  = gid / PPW;
    int hp = t % HP;
    int t2 = t / HP;
    int cp = t2 % NCP;
    int b  = t2 / NCP;

    int h = hp - 1;
    bool rv = (h >= 0) && (h < HH);
    const float* p0 = x + (((b * CIN + 2 * cp)     * HH + h) * WW);
    const float* p1 = x + (((b * CIN + 2 * cp + 1) * HH + h) * WW);

    ulonglong2 outv;
    int w0 = 2 * pp - 1;
    int w1 = 2 * pp;
    bool v0 = rv && (w0 >= 0) && (w0 < WW);
    bool v1 = rv && (w1 >= 0) && (w1 < WW);
    outv.x = v0 ? pk2(p0[w0], p1[w0]) : 0ULL;
    outv.y = v1 ? pk2(p0[w1], p1[w1]) : 0ULL;

    ulonglong2* dst = reinterpret_cast<ulonglong2*>(
        g_X + ((long)((b * NCP + cp) * HP + hp)) * WP) + pp;
    *dst = outv;
}

// ---------------- main kernel ----------------
// 200704 threads = 1568 blocks x 128. grp = g/25088 uniform per block
// (25088 = 196*128). q = g%25088 -> (b, band, w).
__global__ __launch_bounds__(128, 4)
void demolition_conv2d_kernel(const float* __restrict__ Wt,
                              const float* __restrict__ bias,
                              float* __restrict__ out)
{
    __shared__ __align__(16) f2 sW[NCP * NC * 10];   // 2560 B

    const float SCALEf = 15.0f / 9.0f;
    const float INVf   = 9.0f / 15.0f;
    const float MAGICf = 12582912.0f;        // 1.5 * 2^23
    const unsigned MAGB = 0x4B400000u;       // bit pattern of MAGICf
    const unsigned BIAS16 = MAGB * 16u;      // mod 2^32 (wraps cancel)

    int g = blockIdx.x * 128 + threadIdx.x;
    int grp = g / 25088;                 // 0..7, uniform per block
    int q   = g % 25088;
    int w    = q % WW;
    int band = (q / WW) % 28;
    int b    = q / (WW * 28);
    int h0   = band * NS;
    int co_base = grp * NC;

    for (int i = threadIdx.x; i < NCP * NC * 10; i += 128) {
        int e  = i / 10;
        int k  = i % 10;
        int cp = e / NC;
        int lc = e % NC;
        int co = co_base + lc;
        float v0, v1;
        if (k < 9) {
            v0 = Wt[((2 * cp)     * COUT + co) * 9 + k];
            v1 = Wt[((2 * cp + 1) * COUT + co) * 9 + k];
        } else {
            v0 = bias[(2 * cp)     * COUT + co];
            v1 = bias[(2 * cp + 1) * COUT + co];
        }
        sW[i] = pk2(v0 * SCALEf, v1 * SCALEf);
    }
    __syncthreads();

    const f2 MAG2 = pk2(MAGICf, MAGICf);

    // Integer bit-accumulators (low lane = cin 2cp, high lane = cin 2cp+1).
    unsigned accL[NC][NS], accH[NC][NS];
#pragma unroll
    for (int c = 0; c < NC; ++c)
#pragma unroll
        for (int s = 0; s < NS; ++s) { accL[c][s] = 0u; accH[c][s] = 0u; }

    // Padded plane pointer for cp=0: rows h0..h0+5 cover outputs h0..h0+3.
    const f2* A = g_X + ((long)b * NCP * HP + h0) * WP + w;
    const long PSTRIDE = (long)HP * WP;

#pragma unroll 1
    for (int cp = 0; cp < NCP; ++cp) {
        // 6 rows x 3 cols of taps (coalesced LDG.64 in w).
        f2 tp[6][3];
#pragma unroll
        for (int r = 0; r < 6; ++r) {
#pragma unroll
            for (int k = 0; k < 3; ++k)
                tp[r][k] = A[r * WP + k];
        }
        A += PSTRIDE;

        const ulonglong2* wb =
            reinterpret_cast<const ulonglong2*>(&sW[cp * NC * 10]);

#pragma unroll
        for (int c = 0; c < NC; ++c) {
            ulonglong2 w01 = wb[c * 5 + 0];   // w0, w1
            ulonglong2 w23 = wb[c * 5 + 1];   // w2, w3
            ulonglong2 w45 = wb[c * 5 + 2];   // w4, w5
            ulonglong2 w67 = wb[c * 5 + 3];   // w6, w7
            ulonglong2 w8b = wb[c * 5 + 4];   // w8, bias

#pragma unroll
            for (int s = 0; s < NS; ++s) {
                f2 y = w8b.y;
                fma2i(y, tp[s][0],     w01.x);
                fma2i(y, tp[s][1],     w01.y);
                fma2i(y, tp[s][2],     w23.x);
                fma2i(y, tp[s + 1][0], w23.y);
                fma2i(y, tp[s + 1][1], w45.x);
                fma2i(y, tp[s + 1][2], w45.y);
                fma2i(y, tp[s + 2][0], w67.x);
                fma2i(y, tp[s + 2][1], w67.y);
                fma2i(y, tp[s + 2][2], w8b.x);

                add2i(y, MAG2);                    // RNE: bits = 0x4B400000+q
                addbits(accL[c][s], accH[c][s], y); // integer adds (alu pipe)
            }
        }
    }

    // Final: strip 16 magic biases (8 per lane x 2 lanes), convert, scale.
#pragma unroll
    for (int c = 0; c < NC; ++c) {
        int co = co_base + c;
        float* ob = out + ((long)(b * COUT + co) * HH + h0) * WW + w;
#pragma unroll
        for (int s = 0; s < NS; ++s) {
            int qsum = (int)(accL[c][s] + accH[c][s] - BIAS16);
            ob[s * WW] = (float)qsum * INVf;
        }
    }
}

extern "C" void kernel_launch(void* const* d_in, const int* in_sizes, int n_in,
                              void* d_out, int out_size)
{
    const float* x    = (const float*)d_in[0];   // [8,16,112,112]
    const float* Wt   = (const float*)d_in[1];   // [16,32,1,3,3]
    const float* bias = (const float*)d_in[2];   // [16,32]
    float* out        = (float*)d_out;           // [8,32,112,112]

    // NB*NCP*HP*PPW = 415872 -> 1625 blocks of 256 (guarded).
    prepass_kernel<<<1625, 256>>>(x);
    // 200704 threads = 1568 blocks * 128.
    demolition_conv2d_kernel<<<1568, 128>>>(Wt, bias, out);
}